// round 10
// baseline (speedup 1.0000x reference)
#include <cuda_runtime.h>
#include <cstdint>
#include <cstddef>

// E3Hamiltonian: block-diagonal per-edge transform, ROW=282 floats per edge.
// out[n, off + p*m + j] = sum_mm cg[j*m+mm] * in[n, off + p*m + mm]
// Blocks: ss(off0,np6,m1) sp(off6,np9,m3) sd(off33,np6,m5)
//         pp(off63,np6,m9) pd(off117,np6,m15) dd(off207,np3,m25)

#define ROW 282
#define TILE 30                           // 600000 % 30 == 0 -> 20000 tiles
#define THREADS 256
#define TILE_FLOATS (TILE * ROW)          // 8460
#define TILE_BYTES  (TILE_FLOATS * 4)     // 33840
#define CG_TOTAL 1104
#define SMEM_TOTAL (2 * TILE_BYTES + CG_TOTAL * 4 + 16)  // 72112 B -> 3 CTAs/SM

// ---------------- PTX helpers ----------------
__device__ __forceinline__ uint32_t smem_u32(const void* p) {
    return (uint32_t)__cvta_generic_to_shared(p);
}
__device__ __forceinline__ void mbar_init(uint32_t mbar, uint32_t count) {
    asm volatile("mbarrier.init.shared.b64 [%0], %1;" :: "r"(mbar), "r"(count) : "memory");
}
__device__ __forceinline__ void mbar_expect_tx(uint32_t mbar, uint32_t bytes) {
    asm volatile("mbarrier.arrive.expect_tx.shared::cta.b64 _, [%0], %1;"
                 :: "r"(mbar), "r"(bytes) : "memory");
}
__device__ __forceinline__ void mbar_wait(uint32_t mbar, uint32_t parity) {
    asm volatile(
        "{\n\t.reg .pred P;\n\t"
        "WL_%=:\n\t"
        "mbarrier.try_wait.parity.acquire.cta.shared::cta.b64 P, [%0], %1, 0x989680;\n\t"
        "@P bra.uni WD_%=;\n\t"
        "bra.uni WL_%=;\n\t"
        "WD_%=:\n\t}"
        :: "r"(mbar), "r"(parity) : "memory");
}
__device__ __forceinline__ void tma_load_1d(uint32_t dst_smem, const void* src_gmem,
                                            uint32_t bytes, uint32_t mbar) {
    asm volatile(
        "cp.async.bulk.shared::cta.global.mbarrier::complete_tx::bytes [%0], [%1], %2, [%3];"
        :: "r"(dst_smem), "l"(src_gmem), "r"(bytes), "r"(mbar) : "memory");
}
__device__ __forceinline__ void tma_store_1d(void* dst_gmem, uint32_t src_smem, uint32_t bytes) {
    asm volatile(
        "cp.async.bulk.global.shared::cta.bulk_group [%0], [%1], %2;"
        :: "l"(dst_gmem), "r"(src_smem), "r"(bytes) : "memory");
}
__device__ __forceinline__ void tma_commit() {
    asm volatile("cp.async.bulk.commit_group;" ::: "memory");
}
__device__ __forceinline__ void tma_wait_all() {
    asm volatile("cp.async.bulk.wait_group 0;" ::: "memory");
}
__device__ __forceinline__ void fence_async_shared() {
    asm volatile("fence.proxy.async.shared::cta;" ::: "memory");
}

// packed f32x2 ops (sm_100+): one instruction = 2 fp32 FMA lanes
#define PACK2(d, lo, hi) asm("mov.b64 %0, {%1, %2};" : "=l"(d) : "f"(lo), "f"(hi))
#define UNPACK2(lo, hi, d) asm("mov.b64 {%0, %1}, %2;" : "=f"(lo), "=f"(hi) : "l"(d))
#define FMA2(acc, c, x) asm("fma.rn.f32x2 %0, %1, %2, %0;" : "+l"(acc) : "l"(c), "l"(x))

// ---------------- compute ----------------
// One m x m matvec, in place on this lane's row, using packed f32x2 FMA.
// cg rows padded to MP floats (16B aligned, zero-filled) -> read as ulonglong2.
template <int M, int MP>
__device__ __forceinline__ void task(float* __restrict__ r,
                                     const float* __restrict__ cg, int col) {
    if (M == 1) { r[col] = cg[0] * r[col]; return; }
    constexpr int NP2 = MP / 2;   // f32x2 pairs per padded row
    unsigned long long x2[NP2];
#pragma unroll
    for (int i = 0; i < NP2; i++) {
        float lo = (2 * i     < M) ? r[col + 2 * i]     : 0.f;
        float hi = (2 * i + 1 < M) ? r[col + 2 * i + 1] : 0.f;
        PACK2(x2[i], lo, hi);
    }
#pragma unroll
    for (int j = 0; j < M; j++) {
        const ulonglong2* c2 = reinterpret_cast<const ulonglong2*>(cg + j * MP);
        unsigned long long acc = 0ull;    // packed (0.f, 0.f)
#pragma unroll
        for (int k = 0; k < MP / 4; k++) {
            ulonglong2 c = c2[k];         // one LDS.128 = 2 f32x2 coef pairs
            FMA2(acc, c.x, x2[2 * k]);
            FMA2(acc, c.y, x2[2 * k + 1]);
        }
        float a0, a1;
        UNPACK2(a0, a1, acc);
        r[col + j] = a0 + a1;             // x2 cached in regs -> in-place safe
    }
}

// warp-partitioned task dispatch; warps own disjoint column ranges, lane = edge.
__device__ __forceinline__ void compute_row(float* __restrict__ r,
                                            const float* __restrict__ s_cg, int warp) {
    switch (warp) {
        case 0: task<25, 28>(r, s_cg + 404, 207); break;
        case 1: task<25, 28>(r, s_cg + 404, 232); break;
        case 2: task<25, 28>(r, s_cg + 404, 257); break;
        case 3: task<15, 16>(r, s_cg + 164, 117);
                task<15, 16>(r, s_cg + 164, 132); break;
        case 4: task<15, 16>(r, s_cg + 164, 147);
                task<15, 16>(r, s_cg + 164, 162); break;
        case 5: task<15, 16>(r, s_cg + 164, 177);
                task<15, 16>(r, s_cg + 164, 192); break;
        case 6: {
#pragma unroll
            for (int p = 0; p < 5; p++) task<9, 12>(r, s_cg + 56, 63 + 9 * p);
            break;
        }
        default: {  // warp 7
            task<9, 12>(r, s_cg + 56, 108);
#pragma unroll
            for (int p = 0; p < 6; p++) task<5, 8>(r, s_cg + 16, 33 + 5 * p);
#pragma unroll
            for (int p = 0; p < 9; p++) task<3, 4>(r, s_cg + 4, 6 + 3 * p);
#pragma unroll
            for (int p = 0; p < 6; p++) task<1, 4>(r, s_cg + 0, p);
            break;
        }
    }
}

__device__ __forceinline__ void fill_cg(float* __restrict__ dst, const float* __restrict__ src,
                                        int m, int mp, int tid) {
    int total = m * mp;
    for (int i = tid; i < total; i += THREADS) {
        int row = i / mp, c = i - row * mp;
        dst[i] = (c < m) ? src[row * m + c] : 0.f;
    }
}

extern __shared__ __align__(128) unsigned char dynsmem[];

__global__ __launch_bounds__(THREADS, 3)
void e3h_kernel(const float* __restrict__ ef,
                const float* __restrict__ cg_ss, const float* __restrict__ cg_sp,
                const float* __restrict__ cg_sd, const float* __restrict__ cg_pp,
                const float* __restrict__ cg_pd, const float* __restrict__ cg_dd,
                float* __restrict__ out, int n, int ntiles) {
    float* buf0 = reinterpret_cast<float*>(dynsmem);
    float* buf1 = buf0 + TILE_FLOATS;
    float* s_cg = buf1 + TILE_FLOATS;
    unsigned long long* mb = reinterpret_cast<unsigned long long*>(s_cg + CG_TOTAL);

    const int tid = threadIdx.x;
    const int lane = tid & 31;
    const int warp = tid >> 5;

    fill_cg(s_cg + 0,   cg_ss, 1, 4,  tid);
    fill_cg(s_cg + 4,   cg_sp, 3, 4,  tid);
    fill_cg(s_cg + 16,  cg_sd, 5, 8,  tid);
    fill_cg(s_cg + 56,  cg_pp, 9, 12, tid);
    fill_cg(s_cg + 164, cg_pd, 15, 16, tid);
    fill_cg(s_cg + 404, cg_dd, 25, 28, tid);

    const uint32_t mbad0 = smem_u32(mb);
    const uint32_t mbad1 = smem_u32(mb + 1);
    const uint32_t sb0 = smem_u32(buf0);
    const uint32_t sb1 = smem_u32(buf1);
    if (tid == 0) { mbar_init(mbad0, 1); mbar_init(mbad1, 1); }
    __syncthreads();

    const int bid = blockIdx.x;
    const int grid = gridDim.x;
    const int cnt = (bid < ntiles) ? (ntiles - bid + grid - 1) / grid : 0;

    if (cnt > 0 && tid == 0) {
        mbar_expect_tx(mbad0, TILE_BYTES);
        tma_load_1d(sb0, ef + (size_t)bid * TILE_FLOATS, TILE_BYTES, mbad0);
    }

    for (int k = 0; k < cnt; k++) {
        const size_t tile = (size_t)bid + (size_t)k * grid;
        if (tid == 0 && k + 1 < cnt) {
            // buffer (k+1)&1 was last read by store of tile k-1 -> drain stores first
            tma_wait_all();
            const uint32_t mbn = ((k + 1) & 1) ? mbad1 : mbad0;
            const uint32_t sbn = ((k + 1) & 1) ? sb1 : sb0;
            mbar_expect_tx(mbn, TILE_BYTES);
            tma_load_1d(sbn, ef + (tile + grid) * TILE_FLOATS, TILE_BYTES, mbn);
        }
        mbar_wait((k & 1) ? mbad1 : mbad0, (k >> 1) & 1);

        float* s = (k & 1) ? buf1 : buf0;
        if (lane < TILE) compute_row(s + lane * ROW, s_cg, warp);
        __syncthreads();

        if (tid == 0) {
            fence_async_shared();
            tma_store_1d(out + tile * TILE_FLOATS, (k & 1) ? sb1 : sb0, TILE_BYTES);
            tma_commit();
        }
    }

    // ---- remainder edges (600000 % 30 == 0; kept for generality) ----
    const int rem = n - ntiles * TILE;
    if (rem > 0 && bid == 0) {
        if (tid == 0) tma_wait_all();
        __syncthreads();
        const size_t base = (size_t)ntiles * TILE_FLOATS;
        const int cntf = rem * ROW;
        for (int i = tid; i < cntf; i += THREADS) buf0[i] = ef[base + i];
        __syncthreads();
        if (lane < rem) compute_row(buf0 + lane * ROW, s_cg, warp);
        __syncthreads();
        for (int i = tid; i < cntf; i += THREADS) out[base + i] = buf0[i];
    }

    if (tid == 0) tma_wait_all();   // ensure bulk stores complete before exit
}

extern "C" void kernel_launch(void* const* d_in, const int* in_sizes, int n_in,
                              void* d_out, int out_size) {
    const float* ef    = (const float*)d_in[0];
    const float* cg_ss = (const float*)d_in[1];
    const float* cg_sp = (const float*)d_in[2];
    const float* cg_sd = (const float*)d_in[3];
    const float* cg_pp = (const float*)d_in[4];
    const float* cg_pd = (const float*)d_in[5];
    const float* cg_dd = (const float*)d_in[6];
    float* out = (float*)d_out;

    int n = in_sizes[0] / ROW;
    int ntiles = n / TILE;

    int sms = 148;
    cudaDeviceGetAttribute(&sms, cudaDevAttrMultiProcessorCount, 0);
    int grid = 3 * sms;                     // 3 CTAs/SM
    if (ntiles > 0 && grid > ntiles) grid = ntiles;
    if (grid < 1) grid = 1;

    cudaFuncSetAttribute(e3h_kernel, cudaFuncAttributeMaxDynamicSharedMemorySize, SMEM_TOTAL);
    e3h_kernel<<<grid, THREADS, SMEM_TOTAL>>>(ef, cg_ss, cg_sp, cg_sd, cg_pp, cg_pd, cg_dd,
                                              out, n, ntiles);
}

// round 11
// speedup vs baseline: 2.3682x; 2.3682x over previous
#include <cuda_runtime.h>
#include <cstdint>
#include <cstddef>

// E3Hamiltonian: block-diagonal per-edge transform, ROW=282 floats per edge.
// out[n, off + p*m + j] = sum_mm cg[j*m+mm] * in[n, off + p*m + mm]
// Blocks: ss(off0,np6,m1) sp(off6,np9,m3) sd(off33,np6,m5)
//         pp(off63,np6,m9) pd(off117,np6,m15) dd(off207,np3,m25)

#define ROW 282
#define TILE 30                           // 600000 % 30 == 0 -> 20000 tiles
#define THREADS 256
#define TILE_FLOATS (TILE * ROW)          // 8460
#define TILE_BYTES  (TILE_FLOATS * 4)     // 33840
#define CG_TOTAL 1104
#define SMEM_TOTAL (2 * TILE_BYTES + CG_TOTAL * 4 + 16)  // 72112 B -> 3 CTAs/SM

// ---------------- PTX helpers ----------------
__device__ __forceinline__ uint32_t smem_u32(const void* p) {
    return (uint32_t)__cvta_generic_to_shared(p);
}
__device__ __forceinline__ void mbar_init(uint32_t mbar, uint32_t count) {
    asm volatile("mbarrier.init.shared.b64 [%0], %1;" :: "r"(mbar), "r"(count) : "memory");
}
__device__ __forceinline__ void mbar_expect_tx(uint32_t mbar, uint32_t bytes) {
    asm volatile("mbarrier.arrive.expect_tx.shared::cta.b64 _, [%0], %1;"
                 :: "r"(mbar), "r"(bytes) : "memory");
}
__device__ __forceinline__ void mbar_wait(uint32_t mbar, uint32_t parity) {
    asm volatile(
        "{\n\t.reg .pred P;\n\t"
        "WL_%=:\n\t"
        "mbarrier.try_wait.parity.acquire.cta.shared::cta.b64 P, [%0], %1, 0x989680;\n\t"
        "@P bra.uni WD_%=;\n\t"
        "bra.uni WL_%=;\n\t"
        "WD_%=:\n\t}"
        :: "r"(mbar), "r"(parity) : "memory");
}
__device__ __forceinline__ void tma_load_1d(uint32_t dst_smem, const void* src_gmem,
                                            uint32_t bytes, uint32_t mbar) {
    asm volatile(
        "cp.async.bulk.shared::cta.global.mbarrier::complete_tx::bytes [%0], [%1], %2, [%3];"
        :: "r"(dst_smem), "l"(src_gmem), "r"(bytes), "r"(mbar) : "memory");
}
__device__ __forceinline__ void tma_store_1d(void* dst_gmem, uint32_t src_smem, uint32_t bytes) {
    asm volatile(
        "cp.async.bulk.global.shared::cta.bulk_group [%0], [%1], %2;"
        :: "l"(dst_gmem), "r"(src_smem), "r"(bytes) : "memory");
}
__device__ __forceinline__ void tma_commit() {
    asm volatile("cp.async.bulk.commit_group;" ::: "memory");
}
__device__ __forceinline__ void tma_wait_all() {
    asm volatile("cp.async.bulk.wait_group 0;" ::: "memory");
}
__device__ __forceinline__ void fence_async_shared() {
    asm volatile("fence.proxy.async.shared::cta;" ::: "memory");
}

// ---------------- compute ----------------
// One m x m matvec, in place on this lane's row. cg rows padded to MP (16B).
// Output rows processed in PAIRS with 2 accumulators each -> 4 independent
// FFMA chains in flight, halving exposed dependency latency vs 1 chain.
template <int M, int MP>
__device__ __forceinline__ void task(float* __restrict__ r,
                                     const float* __restrict__ cg, int col) {
    float in[M];
#pragma unroll
    for (int mm = 0; mm < M; mm++) in[mm] = r[col + mm];
#pragma unroll
    for (int j = 0; j < M - 1; j += 2) {
        const float4* ca = reinterpret_cast<const float4*>(cg + j * MP);
        const float4* cb = reinterpret_cast<const float4*>(cg + (j + 1) * MP);
        float a0 = 0.f, a1 = 0.f, b0 = 0.f, b1 = 0.f;
#pragma unroll
        for (int k = 0; k < MP / 4; k++) {
            float4 x = ca[k];
            float4 y = cb[k];
            if (4 * k + 0 < M) { a0 += x.x * in[4 * k + 0]; b0 += y.x * in[4 * k + 0]; }
            if (4 * k + 1 < M) { a1 += x.y * in[4 * k + 1]; b1 += y.y * in[4 * k + 1]; }
            if (4 * k + 2 < M) { a0 += x.z * in[4 * k + 2]; b0 += y.z * in[4 * k + 2]; }
            if (4 * k + 3 < M) { a1 += x.w * in[4 * k + 3]; b1 += y.w * in[4 * k + 3]; }
        }
        r[col + j] = a0 + a1;
        r[col + j + 1] = b0 + b1;
    }
    if (M & 1) {   // last row for odd M
        constexpr int j = M - 1;
        const float4* ca = reinterpret_cast<const float4*>(cg + j * MP);
        float a0 = 0.f, a1 = 0.f;
#pragma unroll
        for (int k = 0; k < MP / 4; k++) {
            float4 x = ca[k];
            if (4 * k + 0 < M) a0 += x.x * in[4 * k + 0];
            if (4 * k + 1 < M) a1 += x.y * in[4 * k + 1];
            if (4 * k + 2 < M) a0 += x.z * in[4 * k + 2];
            if (4 * k + 3 < M) a1 += x.w * in[4 * k + 3];
        }
        r[col + j] = a0 + a1;
    }
}

// warp-partitioned task dispatch; warps own disjoint column ranges, lane = edge.
__device__ __forceinline__ void compute_row(float* __restrict__ r,
                                            const float* __restrict__ s_cg, int warp) {
    switch (warp) {
        case 0: task<25, 28>(r, s_cg + 404, 207); break;
        case 1: task<25, 28>(r, s_cg + 404, 232); break;
        case 2: task<25, 28>(r, s_cg + 404, 257); break;
        case 3: task<15, 16>(r, s_cg + 164, 117);
                task<15, 16>(r, s_cg + 164, 132); break;
        case 4: task<15, 16>(r, s_cg + 164, 147);
                task<15, 16>(r, s_cg + 164, 162); break;
        case 5: task<15, 16>(r, s_cg + 164, 177);
                task<15, 16>(r, s_cg + 164, 192); break;
        case 6: {
#pragma unroll
            for (int p = 0; p < 5; p++) task<9, 12>(r, s_cg + 56, 63 + 9 * p);
            break;
        }
        default: {  // warp 7
            task<9, 12>(r, s_cg + 56, 108);
#pragma unroll
            for (int p = 0; p < 6; p++) task<5, 8>(r, s_cg + 16, 33 + 5 * p);
#pragma unroll
            for (int p = 0; p < 9; p++) task<3, 4>(r, s_cg + 4, 6 + 3 * p);
#pragma unroll
            for (int p = 0; p < 6; p++) task<1, 4>(r, s_cg + 0, p);
            break;
        }
    }
}

__device__ __forceinline__ void fill_cg(float* __restrict__ dst, const float* __restrict__ src,
                                        int m, int mp, int tid) {
    int total = m * mp;
    for (int i = tid; i < total; i += THREADS) {
        int row = i / mp, c = i - row * mp;
        dst[i] = (c < m) ? src[row * m + c] : 0.f;
    }
}

extern __shared__ __align__(128) unsigned char dynsmem[];

__global__ __launch_bounds__(THREADS, 3)
void e3h_kernel(const float* __restrict__ ef,
                const float* __restrict__ cg_ss, const float* __restrict__ cg_sp,
                const float* __restrict__ cg_sd, const float* __restrict__ cg_pp,
                const float* __restrict__ cg_pd, const float* __restrict__ cg_dd,
                float* __restrict__ out, int n, int ntiles) {
    float* buf0 = reinterpret_cast<float*>(dynsmem);
    float* buf1 = buf0 + TILE_FLOATS;
    float* s_cg = buf1 + TILE_FLOATS;
    unsigned long long* mb = reinterpret_cast<unsigned long long*>(s_cg + CG_TOTAL);

    const int tid = threadIdx.x;
    const int lane = tid & 31;
    const int warp = tid >> 5;

    fill_cg(s_cg + 0,   cg_ss, 1, 4,  tid);
    fill_cg(s_cg + 4,   cg_sp, 3, 4,  tid);
    fill_cg(s_cg + 16,  cg_sd, 5, 8,  tid);
    fill_cg(s_cg + 56,  cg_pp, 9, 12, tid);
    fill_cg(s_cg + 164, cg_pd, 15, 16, tid);
    fill_cg(s_cg + 404, cg_dd, 25, 28, tid);

    const uint32_t mbad0 = smem_u32(mb);
    const uint32_t mbad1 = smem_u32(mb + 1);
    const uint32_t sb0 = smem_u32(buf0);
    const uint32_t sb1 = smem_u32(buf1);
    if (tid == 0) { mbar_init(mbad0, 1); mbar_init(mbad1, 1); }
    __syncthreads();

    const int bid = blockIdx.x;
    const int grid = gridDim.x;
    const int cnt = (bid < ntiles) ? (ntiles - bid + grid - 1) / grid : 0;

    if (cnt > 0 && tid == 0) {
        mbar_expect_tx(mbad0, TILE_BYTES);
        tma_load_1d(sb0, ef + (size_t)bid * TILE_FLOATS, TILE_BYTES, mbad0);
    }

    for (int k = 0; k < cnt; k++) {
        const size_t tile = (size_t)bid + (size_t)k * grid;
        if (tid == 0 && k + 1 < cnt) {
            // buffer (k+1)&1 was last read by store of tile k-1 -> drain stores first
            tma_wait_all();
            const uint32_t mbn = ((k + 1) & 1) ? mbad1 : mbad0;
            const uint32_t sbn = ((k + 1) & 1) ? sb1 : sb0;
            mbar_expect_tx(mbn, TILE_BYTES);
            tma_load_1d(sbn, ef + (tile + grid) * TILE_FLOATS, TILE_BYTES, mbn);
        }
        mbar_wait((k & 1) ? mbad1 : mbad0, (k >> 1) & 1);

        float* s = (k & 1) ? buf1 : buf0;
        if (lane < TILE) compute_row(s + lane * ROW, s_cg, warp);
        __syncthreads();

        if (tid == 0) {
            fence_async_shared();
            tma_store_1d(out + tile * TILE_FLOATS, (k & 1) ? sb1 : sb0, TILE_BYTES);
            tma_commit();
        }
    }

    // ---- remainder edges (600000 % 30 == 0; kept for generality) ----
    const int rem = n - ntiles * TILE;
    if (rem > 0 && bid == 0) {
        if (tid == 0) tma_wait_all();
        __syncthreads();
        const size_t base = (size_t)ntiles * TILE_FLOATS;
        const int cntf = rem * ROW;
        for (int i = tid; i < cntf; i += THREADS) buf0[i] = ef[base + i];
        __syncthreads();
        if (lane < rem) compute_row(buf0 + lane * ROW, s_cg, warp);
        __syncthreads();
        for (int i = tid; i < cntf; i += THREADS) out[base + i] = buf0[i];
    }

    if (tid == 0) tma_wait_all();   // ensure bulk stores complete before exit
}

extern "C" void kernel_launch(void* const* d_in, const int* in_sizes, int n_in,
                              void* d_out, int out_size) {
    const float* ef    = (const float*)d_in[0];
    const float* cg_ss = (const float*)d_in[1];
    const float* cg_sp = (const float*)d_in[2];
    const float* cg_sd = (const float*)d_in[3];
    const float* cg_pp = (const float*)d_in[4];
    const float* cg_pd = (const float*)d_in[5];
    const float* cg_dd = (const float*)d_in[6];
    float* out = (float*)d_out;

    int n = in_sizes[0] / ROW;
    int ntiles = n / TILE;

    int sms = 148;
    cudaDeviceGetAttribute(&sms, cudaDevAttrMultiProcessorCount, 0);
    int grid = 3 * sms;                     // 3 CTAs/SM
    if (ntiles > 0 && grid > ntiles) grid = ntiles;
    if (grid < 1) grid = 1;

    cudaFuncSetAttribute(e3h_kernel, cudaFuncAttributeMaxDynamicSharedMemorySize, SMEM_TOTAL);
    e3h_kernel<<<grid, THREADS, SMEM_TOTAL>>>(ef, cg_ss, cg_sp, cg_sd, cg_pp, cg_pd, cg_dd,
                                              out, n, ntiles);
}

// round 12
// speedup vs baseline: 3.2586x; 1.3760x over previous
#include <cuda_runtime.h>
#include <cstdint>
#include <cstddef>

// E3Hamiltonian: block-diagonal per-edge transform, ROW=282 floats per edge.
// out[n, off + p*m + j] = sum_mm cg[j*m+mm] * in[n, off + p*m + mm]
// Blocks: ss(off0,np6,m1) sp(off6,np9,m3) sd(off33,np6,m5)
//         pp(off63,np6,m9) pd(off117,np6,m15) dd(off207,np3,m25)

#define ROW 282
#define TILE 30                           // 600000 % 30 == 0 -> 20000 tiles
#define THREADS 256
#define TILE_FLOATS (TILE * ROW)          // 8460
#define TILE_BYTES  (TILE_FLOATS * 4)     // 33840
#define CG_TOTAL 1104
#define SMEM_TOTAL (2 * TILE_BYTES + CG_TOTAL * 4 + 16)  // 72112 B -> 3 CTAs/SM

// ---------------- PTX helpers ----------------
__device__ __forceinline__ uint32_t smem_u32(const void* p) {
    return (uint32_t)__cvta_generic_to_shared(p);
}
__device__ __forceinline__ void mbar_init(uint32_t mbar, uint32_t count) {
    asm volatile("mbarrier.init.shared.b64 [%0], %1;" :: "r"(mbar), "r"(count) : "memory");
}
__device__ __forceinline__ void mbar_expect_tx(uint32_t mbar, uint32_t bytes) {
    asm volatile("mbarrier.arrive.expect_tx.shared::cta.b64 _, [%0], %1;"
                 :: "r"(mbar), "r"(bytes) : "memory");
}
__device__ __forceinline__ void mbar_wait(uint32_t mbar, uint32_t parity) {
    asm volatile(
        "{\n\t.reg .pred P;\n\t"
        "WL_%=:\n\t"
        "mbarrier.try_wait.parity.acquire.cta.shared::cta.b64 P, [%0], %1, 0x989680;\n\t"
        "@P bra.uni WD_%=;\n\t"
        "bra.uni WL_%=;\n\t"
        "WD_%=:\n\t}"
        :: "r"(mbar), "r"(parity) : "memory");
}
__device__ __forceinline__ void tma_load_1d(uint32_t dst_smem, const void* src_gmem,
                                            uint32_t bytes, uint32_t mbar) {
    asm volatile(
        "cp.async.bulk.shared::cta.global.mbarrier::complete_tx::bytes [%0], [%1], %2, [%3];"
        :: "r"(dst_smem), "l"(src_gmem), "r"(bytes), "r"(mbar) : "memory");
}
__device__ __forceinline__ void tma_store_1d(void* dst_gmem, uint32_t src_smem, uint32_t bytes) {
    asm volatile(
        "cp.async.bulk.global.shared::cta.bulk_group [%0], [%1], %2;"
        :: "l"(dst_gmem), "r"(src_smem), "r"(bytes) : "memory");
}
__device__ __forceinline__ void tma_commit() {
    asm volatile("cp.async.bulk.commit_group;" ::: "memory");
}
__device__ __forceinline__ void tma_wait_all() {
    asm volatile("cp.async.bulk.wait_group 0;" ::: "memory");
}
__device__ __forceinline__ void fence_async_shared() {
    asm volatile("fence.proxy.async.shared::cta;" ::: "memory");
}

// ---------------- compute ----------------
// Single-pair m x m matvec, in place (R2/R9-proven). cg rows padded to MP.
template <int M, int MP>
__device__ __forceinline__ void task(float* __restrict__ r,
                                     const float* __restrict__ cg, int col) {
    float in[M];
#pragma unroll
    for (int mm = 0; mm < M; mm++) in[mm] = r[col + mm];
#pragma unroll
    for (int j = 0; j < M; j++) {
        const float4* c4 = reinterpret_cast<const float4*>(cg + j * MP);
        float acc = 0.f;
#pragma unroll
        for (int k = 0; k < MP / 4; k++) {
            float4 c = c4[k];
            if (4 * k + 0 < M) acc += c.x * in[4 * k + 0];
            if (4 * k + 1 < M) acc += c.y * in[4 * k + 1];
            if (4 * k + 2 < M) acc += c.z * in[4 * k + 2];
            if (4 * k + 3 < M) acc += c.w * in[4 * k + 3];
        }
        r[col + j] = acc;
    }
}

// Multi-pair amortized: NP consecutive pairs of one type; each cg row is
// loaded from smem ONCE and applied to all NP pairs (inputs cached in regs
// first -> in-place safe within the owning warp).
template <int M, int MP, int NP>
__device__ __forceinline__ void task_multi(float* __restrict__ r,
                                           const float* __restrict__ cg, int col) {
    float in[NP][M];
#pragma unroll
    for (int p = 0; p < NP; p++)
#pragma unroll
        for (int mm = 0; mm < M; mm++) in[p][mm] = r[col + p * M + mm];
#pragma unroll
    for (int j = 0; j < M; j++) {
        const float4* c4 = reinterpret_cast<const float4*>(cg + j * MP);
        float acc[NP];
#pragma unroll
        for (int p = 0; p < NP; p++) acc[p] = 0.f;
#pragma unroll
        for (int k = 0; k < MP / 4; k++) {
            float4 c = c4[k];
#pragma unroll
            for (int p = 0; p < NP; p++) {
                if (4 * k + 0 < M) acc[p] += c.x * in[p][4 * k + 0];
                if (4 * k + 1 < M) acc[p] += c.y * in[p][4 * k + 1];
                if (4 * k + 2 < M) acc[p] += c.z * in[p][4 * k + 2];
                if (4 * k + 3 < M) acc[p] += c.w * in[p][4 * k + 3];
            }
        }
#pragma unroll
        for (int p = 0; p < NP; p++) r[col + p * M + j] = acc[p];
    }
}

// warp-partitioned dispatch; warps own disjoint column ranges, lane = edge.
// cg smem bases: ss=0(mp4) sp=4(mp4) sd=16(mp8) pp=56(mp12) pd=164(mp16) dd=404(mp28)
__device__ __forceinline__ void compute_row(float* __restrict__ r,
                                            const float* __restrict__ s_cg, int warp) {
    switch (warp) {
        case 0: task<25, 28>(r, s_cg + 404, 207); break;
        case 1: task<25, 28>(r, s_cg + 404, 232); break;
        case 2: task<25, 28>(r, s_cg + 404, 257); break;
        case 3: task_multi<15, 16, 2>(r, s_cg + 164, 117); break;
        case 4: task_multi<15, 16, 2>(r, s_cg + 164, 147); break;
        case 5: task_multi<15, 16, 2>(r, s_cg + 164, 177); break;
        case 6: task_multi<9, 12, 5>(r, s_cg + 56, 63); break;
        default:  // warp 7
            task<9, 12>(r, s_cg + 56, 108);
            task_multi<5, 8, 6>(r, s_cg + 16, 33);
            task_multi<3, 4, 9>(r, s_cg + 4, 6);
            task_multi<1, 4, 6>(r, s_cg + 0, 0);
            break;
    }
}

__device__ __forceinline__ void fill_cg(float* __restrict__ dst, const float* __restrict__ src,
                                        int m, int mp, int tid) {
    int total = m * mp;
    for (int i = tid; i < total; i += THREADS) {
        int row = i / mp, c = i - row * mp;
        dst[i] = (c < m) ? src[row * m + c] : 0.f;
    }
}

extern __shared__ __align__(128) unsigned char dynsmem[];

__global__ __launch_bounds__(THREADS, 3)
void e3h_kernel(const float* __restrict__ ef,
                const float* __restrict__ cg_ss, const float* __restrict__ cg_sp,
                const float* __restrict__ cg_sd, const float* __restrict__ cg_pp,
                const float* __restrict__ cg_pd, const float* __restrict__ cg_dd,
                float* __restrict__ out, int n, int ntiles) {
    float* buf0 = reinterpret_cast<float*>(dynsmem);
    float* buf1 = buf0 + TILE_FLOATS;
    float* s_cg = buf1 + TILE_FLOATS;
    unsigned long long* mb = reinterpret_cast<unsigned long long*>(s_cg + CG_TOTAL);

    const int tid = threadIdx.x;
    const int lane = tid & 31;
    const int warp = tid >> 5;

    fill_cg(s_cg + 0,   cg_ss, 1, 4,  tid);
    fill_cg(s_cg + 4,   cg_sp, 3, 4,  tid);
    fill_cg(s_cg + 16,  cg_sd, 5, 8,  tid);
    fill_cg(s_cg + 56,  cg_pp, 9, 12, tid);
    fill_cg(s_cg + 164, cg_pd, 15, 16, tid);
    fill_cg(s_cg + 404, cg_dd, 25, 28, tid);

    const uint32_t mbad0 = smem_u32(mb);
    const uint32_t mbad1 = smem_u32(mb + 1);
    const uint32_t sb0 = smem_u32(buf0);
    const uint32_t sb1 = smem_u32(buf1);
    if (tid == 0) { mbar_init(mbad0, 1); mbar_init(mbad1, 1); }
    __syncthreads();

    const int bid = blockIdx.x;
    const int grid = gridDim.x;
    const int cnt = (bid < ntiles) ? (ntiles - bid + grid - 1) / grid : 0;

    if (cnt > 0 && tid == 0) {
        mbar_expect_tx(mbad0, TILE_BYTES);
        tma_load_1d(sb0, ef + (size_t)bid * TILE_FLOATS, TILE_BYTES, mbad0);
    }

    for (int k = 0; k < cnt; k++) {
        const size_t tile = (size_t)bid + (size_t)k * grid;
        if (tid == 0 && k + 1 < cnt) {
            // buffer (k+1)&1 was last read by store of tile k-1 -> drain stores first
            tma_wait_all();
            const uint32_t mbn = ((k + 1) & 1) ? mbad1 : mbad0;
            const uint32_t sbn = ((k + 1) & 1) ? sb1 : sb0;
            mbar_expect_tx(mbn, TILE_BYTES);
            tma_load_1d(sbn, ef + (tile + grid) * TILE_FLOATS, TILE_BYTES, mbn);
        }
        mbar_wait((k & 1) ? mbad1 : mbad0, (k >> 1) & 1);

        float* s = (k & 1) ? buf1 : buf0;
        if (lane < TILE) compute_row(s + lane * ROW, s_cg, warp);
        __syncthreads();

        if (tid == 0) {
            fence_async_shared();
            tma_store_1d(out + tile * TILE_FLOATS, (k & 1) ? sb1 : sb0, TILE_BYTES);
            tma_commit();
        }
    }

    // ---- remainder edges (600000 % 30 == 0; kept for generality) ----
    const int rem = n - ntiles * TILE;
    if (rem > 0 && bid == 0) {
        if (tid == 0) tma_wait_all();
        __syncthreads();
        const size_t base = (size_t)ntiles * TILE_FLOATS;
        const int cntf = rem * ROW;
        for (int i = tid; i < cntf; i += THREADS) buf0[i] = ef[base + i];
        __syncthreads();
        if (lane < rem) compute_row(buf0 + lane * ROW, s_cg, warp);
        __syncthreads();
        for (int i = tid; i < cntf; i += THREADS) out[base + i] = buf0[i];
    }

    if (tid == 0) tma_wait_all();   // ensure bulk stores complete before exit
}

extern "C" void kernel_launch(void* const* d_in, const int* in_sizes, int n_in,
                              void* d_out, int out_size) {
    const float* ef    = (const float*)d_in[0];
    const float* cg_ss = (const float*)d_in[1];
    const float* cg_sp = (const float*)d_in[2];
    const float* cg_sd = (const float*)d_in[3];
    const float* cg_pp = (const float*)d_in[4];
    const float* cg_pd = (const float*)d_in[5];
    const float* cg_dd = (const float*)d_in[6];
    float* out = (float*)d_out;

    int n = in_sizes[0] / ROW;
    int ntiles = n / TILE;

    int sms = 148;
    cudaDeviceGetAttribute(&sms, cudaDevAttrMultiProcessorCount, 0);
    int grid = 3 * sms;                     // 3 CTAs/SM
    if (ntiles > 0 && grid > ntiles) grid = ntiles;
    if (grid < 1) grid = 1;

    cudaFuncSetAttribute(e3h_kernel, cudaFuncAttributeMaxDynamicSharedMemorySize, SMEM_TOTAL);
    e3h_kernel<<<grid, THREADS, SMEM_TOTAL>>>(ef, cg_ss, cg_sp, cg_sd, cg_pp, cg_pd, cg_dd,
                                              out, n, ntiles);
}

// round 15
// speedup vs baseline: 3.3346x; 1.0233x over previous
#include <cuda_runtime.h>
#include <cstdint>
#include <cstddef>

// E3Hamiltonian: block-diagonal per-edge transform, ROW=282 floats per edge.
// out[n, off + p*m + j] = sum_mm cg[j*m+mm] * in[n, off + p*m + mm]
// Blocks: ss(off0,np6,m1) sp(off6,np9,m3) sd(off33,np6,m5)
//         pp(off63,np6,m9) pd(off117,np6,m15) dd(off207,np3,m25)

#define ROW 282
#define TILE 30                           // 600000 % 30 == 0 -> 20000 tiles
#define THREADS 256
#define PRODUCER 224                      // lane 0 of warp 7 (lightest warp)
#define TILE_FLOATS (TILE * ROW)          // 8460
#define TILE_BYTES  (TILE_FLOATS * 4)     // 33840
#define CG_TOTAL 1104
#define SMEM_TOTAL (2 * TILE_BYTES + CG_TOTAL * 4 + 16)  // 72112 B -> 3 CTAs/SM

// ---------------- PTX helpers ----------------
__device__ __forceinline__ uint32_t smem_u32(const void* p) {
    return (uint32_t)__cvta_generic_to_shared(p);
}
__device__ __forceinline__ void mbar_init(uint32_t mbar, uint32_t count) {
    asm volatile("mbarrier.init.shared.b64 [%0], %1;" :: "r"(mbar), "r"(count) : "memory");
}
__device__ __forceinline__ void mbar_expect_tx(uint32_t mbar, uint32_t bytes) {
    asm volatile("mbarrier.arrive.expect_tx.shared::cta.b64 _, [%0], %1;"
                 :: "r"(mbar), "r"(bytes) : "memory");
}
__device__ __forceinline__ void mbar_wait(uint32_t mbar, uint32_t parity) {
    asm volatile(
        "{\n\t.reg .pred P;\n\t"
        "WL_%=:\n\t"
        "mbarrier.try_wait.parity.acquire.cta.shared::cta.b64 P, [%0], %1, 0x989680;\n\t"
        "@P bra.uni WD_%=;\n\t"
        "bra.uni WL_%=;\n\t"
        "WD_%=:\n\t}"
        :: "r"(mbar), "r"(parity) : "memory");
}
__device__ __forceinline__ void tma_load_1d(uint32_t dst_smem, const void* src_gmem,
                                            uint32_t bytes, uint32_t mbar) {
    asm volatile(
        "cp.async.bulk.shared::cta.global.mbarrier::complete_tx::bytes [%0], [%1], %2, [%3];"
        :: "r"(dst_smem), "l"(src_gmem), "r"(bytes), "r"(mbar) : "memory");
}
__device__ __forceinline__ void tma_store_1d(void* dst_gmem, uint32_t src_smem, uint32_t bytes) {
    asm volatile(
        "cp.async.bulk.global.shared::cta.bulk_group [%0], [%1], %2;"
        :: "l"(dst_gmem), "r"(src_smem), "r"(bytes) : "memory");
}
__device__ __forceinline__ void tma_commit() {
    asm volatile("cp.async.bulk.commit_group;" ::: "memory");
}
__device__ __forceinline__ void tma_wait_all() {
    asm volatile("cp.async.bulk.wait_group 0;" ::: "memory");
}
__device__ __forceinline__ void fence_async_shared() {
    asm volatile("fence.proxy.async.shared::cta;" ::: "memory");
}

// ---------------- compute ----------------
// Single-pair m x m matvec, in place (R2/R9-proven). cg rows padded to MP.
template <int M, int MP>
__device__ __forceinline__ void task(float* __restrict__ r,
                                     const float* __restrict__ cg, int col) {
    float in[M];
#pragma unroll
    for (int mm = 0; mm < M; mm++) in[mm] = r[col + mm];
#pragma unroll
    for (int j = 0; j < M; j++) {
        const float4* c4 = reinterpret_cast<const float4*>(cg + j * MP);
        float acc = 0.f;
#pragma unroll
        for (int k = 0; k < MP / 4; k++) {
            float4 c = c4[k];
            if (4 * k + 0 < M) acc += c.x * in[4 * k + 0];
            if (4 * k + 1 < M) acc += c.y * in[4 * k + 1];
            if (4 * k + 2 < M) acc += c.z * in[4 * k + 2];
            if (4 * k + 3 < M) acc += c.w * in[4 * k + 3];
        }
        r[col + j] = acc;
    }
}

// Multi-pair amortized: NP consecutive pairs of one type; each cg row is
// loaded from smem ONCE and applied to all NP pairs (inputs cached in regs
// first -> in-place safe within the owning warp).
template <int M, int MP, int NP>
__device__ __forceinline__ void task_multi(float* __restrict__ r,
                                           const float* __restrict__ cg, int col) {
    float in[NP][M];
#pragma unroll
    for (int p = 0; p < NP; p++)
#pragma unroll
        for (int mm = 0; mm < M; mm++) in[p][mm] = r[col + p * M + mm];
#pragma unroll
    for (int j = 0; j < M; j++) {
        const float4* c4 = reinterpret_cast<const float4*>(cg + j * MP);
        float acc[NP];
#pragma unroll
        for (int p = 0; p < NP; p++) acc[p] = 0.f;
#pragma unroll
        for (int k = 0; k < MP / 4; k++) {
            float4 c = c4[k];
#pragma unroll
            for (int p = 0; p < NP; p++) {
                if (4 * k + 0 < M) acc[p] += c.x * in[p][4 * k + 0];
                if (4 * k + 1 < M) acc[p] += c.y * in[p][4 * k + 1];
                if (4 * k + 2 < M) acc[p] += c.z * in[p][4 * k + 2];
                if (4 * k + 3 < M) acc[p] += c.w * in[p][4 * k + 3];
            }
        }
#pragma unroll
        for (int p = 0; p < NP; p++) r[col + p * M + j] = acc[p];
    }
}

// warp-partitioned dispatch; warps own disjoint column ranges, lane = edge.
// cg smem bases: ss=0(mp4) sp=4(mp4) sd=16(mp8) pp=56(mp12) pd=164(mp16) dd=404(mp28)
__device__ __forceinline__ void compute_row(float* __restrict__ r,
                                            const float* __restrict__ s_cg, int warp) {
    switch (warp) {
        case 0: task<25, 28>(r, s_cg + 404, 207); break;
        case 1: task<25, 28>(r, s_cg + 404, 232); break;
        case 2: task<25, 28>(r, s_cg + 404, 257); break;
        case 3: task_multi<15, 16, 2>(r, s_cg + 164, 117); break;
        case 4: task_multi<15, 16, 2>(r, s_cg + 164, 147); break;
        case 5: task_multi<15, 16, 2>(r, s_cg + 164, 177); break;
        case 6: task_multi<9, 12, 5>(r, s_cg + 56, 63); break;
        default:  // warp 7 (also hosts the TMA producer thread, tid 224)
            task<9, 12>(r, s_cg + 56, 108);
            task_multi<5, 8, 6>(r, s_cg + 16, 33);
            task_multi<3, 4, 9>(r, s_cg + 4, 6);
            task_multi<1, 4, 6>(r, s_cg + 0, 0);
            break;
    }
}

__device__ __forceinline__ void fill_cg(float* __restrict__ dst, const float* __restrict__ src,
                                        int m, int mp, int tid) {
    int total = m * mp;
    for (int i = tid; i < total; i += THREADS) {
        int row = i / mp, c = i - row * mp;
        dst[i] = (c < m) ? src[row * m + c] : 0.f;
    }
}

extern __shared__ __align__(128) unsigned char dynsmem[];

__global__ __launch_bounds__(THREADS, 3)
void e3h_kernel(const float* __restrict__ ef,
                const float* __restrict__ cg_ss, const float* __restrict__ cg_sp,
                const float* __restrict__ cg_sd, const float* __restrict__ cg_pp,
                const float* __restrict__ cg_pd, const float* __restrict__ cg_dd,
                float* __restrict__ out, int n, int ntiles) {
    float* buf0 = reinterpret_cast<float*>(dynsmem);
    float* buf1 = buf0 + TILE_FLOATS;
    float* s_cg = buf1 + TILE_FLOATS;
    unsigned long long* mb = reinterpret_cast<unsigned long long*>(s_cg + CG_TOTAL);

    const int tid = threadIdx.x;
    const int lane = tid & 31;
    const int warp = tid >> 5;

    fill_cg(s_cg + 0,   cg_ss, 1, 4,  tid);
    fill_cg(s_cg + 4,   cg_sp, 3, 4,  tid);
    fill_cg(s_cg + 16,  cg_sd, 5, 8,  tid);
    fill_cg(s_cg + 56,  cg_pp, 9, 12, tid);
    fill_cg(s_cg + 164, cg_pd, 15, 16, tid);
    fill_cg(s_cg + 404, cg_dd, 25, 28, tid);

    const uint32_t mbad0 = smem_u32(mb);
    const uint32_t mbad1 = smem_u32(mb + 1);
    const uint32_t sb0 = smem_u32(buf0);
    const uint32_t sb1 = smem_u32(buf1);
    if (tid == 0) { mbar_init(mbad0, 1); mbar_init(mbad1, 1); }
    __syncthreads();

    const int bid = blockIdx.x;
    const int grid = gridDim.x;
    const int cnt = (bid < ntiles) ? (ntiles - bid + grid - 1) / grid : 0;

    // prologue load issued by PRODUCER so all TMA group state lives on one thread
    if (cnt > 0 && tid == PRODUCER) {
        mbar_expect_tx(mbad0, TILE_BYTES);
        tma_load_1d(sb0, ef + (size_t)bid * TILE_FLOATS, TILE_BYTES, mbad0);
    }

    for (int k = 0; k < cnt; k++) {
        const size_t tile = (size_t)bid + (size_t)k * grid;
        if (tid == PRODUCER && k + 1 < cnt) {
            // buffer (k+1)&1 was last read by store of tile k-1 -> drain stores first.
            // This drain now lives on the LIGHT warp (w7), off the dd critical path.
            tma_wait_all();
            const uint32_t mbn = ((k + 1) & 1) ? mbad1 : mbad0;
            const uint32_t sbn = ((k + 1) & 1) ? sb1 : sb0;
            mbar_expect_tx(mbn, TILE_BYTES);
            tma_load_1d(sbn, ef + (tile + grid) * TILE_FLOATS, TILE_BYTES, mbn);
        }
        mbar_wait((k & 1) ? mbad1 : mbad0, (k >> 1) & 1);

        float* s = (k & 1) ? buf1 : buf0;
        if (lane < TILE) compute_row(s + lane * ROW, s_cg, warp);
        __syncthreads();

        if (tid == PRODUCER) {
            fence_async_shared();
            tma_store_1d(out + tile * TILE_FLOATS, (k & 1) ? sb1 : sb0, TILE_BYTES);
            tma_commit();
        }
    }

    // ---- remainder edges (600000 % 30 == 0; kept for generality) ----
    const int rem = n - ntiles * TILE;
    if (rem > 0 && bid == 0) {
        if (tid == PRODUCER) tma_wait_all();
        __syncthreads();
        const size_t base = (size_t)ntiles * TILE_FLOATS;
        const int cntf = rem * ROW;
        for (int i = tid; i < cntf; i += THREADS) buf0[i] = ef[base + i];
        __syncthreads();
        if (lane < rem) compute_row(buf0 + lane * ROW, s_cg, warp);
        __syncthreads();
        for (int i = tid; i < cntf; i += THREADS) out[base + i] = buf0[i];
    }

    if (tid == PRODUCER) tma_wait_all();   // drain bulk stores before exit
}

extern "C" void kernel_launch(void* const* d_in, const int* in_sizes, int n_in,
                              void* d_out, int out_size) {
    const float* ef    = (const float*)d_in[0];
    const float* cg_ss = (const float*)d_in[1];
    const float* cg_sp = (const float*)d_in[2];
    const float* cg_sd = (const float*)d_in[3];
    const float* cg_pp = (const float*)d_in[4];
    const float* cg_pd = (const float*)d_in[5];
    const float* cg_dd = (const float*)d_in[6];
    float* out = (float*)d_out;

    int n = in_sizes[0] / ROW;
    int ntiles = n / TILE;

    int sms = 148;
    cudaDeviceGetAttribute(&sms, cudaDevAttrMultiProcessorCount, 0);
    int grid = 3 * sms;                     // 3 CTAs/SM
    if (ntiles > 0 && grid > ntiles) grid = ntiles;
    if (grid < 1) grid = 1;

    cudaFuncSetAttribute(e3h_kernel, cudaFuncAttributeMaxDynamicSharedMemorySize, SMEM_TOTAL);
    e3h_kernel<<<grid, THREADS, SMEM_TOTAL>>>(ef, cg_ss, cg_sp, cg_sd, cg_pp, cg_pd, cg_dd,
                                              out, n, ntiles);
}